// round 17
// baseline (speedup 1.0000x reference)
#include <cuda_runtime.h>
#include <cuda_bf16.h>
#include <math.h>

#define Bn 64
#define Ln 256
#define En 300
#define Mn 50
#define Dn 350
#define HDn 128
#define Gn 512   // 4*HD
#define Hn 256
#define KPAD 352
#define NEGBIG 1e30f

typedef unsigned long long ull;

// Scratch (device globals; no allocation allowed)
__device__ float g_gates_f[Bn*Ln*Gn];
__device__ float g_gates_b[Bn*Ln*Gn];
__device__ float g_hf[Bn*Ln*HDn];
__device__ float g_hb[Bn*Ln*HDn];
__device__ __nv_bfloat16 g_A_hi[(size_t)Bn*Ln*KPAD];
__device__ __nv_bfloat16 g_A_lo[(size_t)Bn*Ln*KPAD];
__device__ __nv_bfloat16 g_B_hi[2*Gn*KPAD];
__device__ __nv_bfloat16 g_B_lo[2*Gn*KPAD];
#define KRQ 24
#define KSQ 8
__device__ ulonglong2 g_wrA[2*KRQ*256];
__device__ ulonglong2 g_wrB[2*KRQ*256];
__device__ ulonglong2 g_wsA[2*KSQ*256];
__device__ ulonglong2 g_wsB[2*KSQ*256];
__device__ float g_cls[Bn];
__device__ float g_spsum[Bn];
__device__ unsigned g_crf_done;

__device__ __forceinline__ float tanha(float x){
    float r; asm("tanh.approx.f32 %0, %1;" : "=f"(r) : "f"(x)); return r;
}
__device__ __forceinline__ float sigf(float x){
    return fmaf(tanha(0.5f*x), 0.5f, 0.5f);
}
__device__ __forceinline__ float lse2(float a, float b){
    float m = fmaxf(a,b);
    return m + __logf(__expf(a-m)+__expf(b-m));
}
// p <- q ∘ p   (q is the EARLIER factor)
__device__ __forceinline__ void mcompose_pre(float q00,float q01,float q10,float q11,
                                             float &p00,float &p01,float &p10,float &p11){
    const float n00 = lse2(q00+p00, q01+p10);
    const float n01 = lse2(q00+p01, q01+p11);
    const float n10 = lse2(q10+p00, q11+p10);
    const float n11 = lse2(q10+p01, q11+p11);
    p00=n00; p01=n01; p10=n10; p11=n11;
}
// p <- p ∘ q   (q is the LATER factor)
__device__ __forceinline__ void mcompose_post(float &p00,float &p01,float &p10,float &p11,
                                              float q00,float q01,float q10,float q11){
    const float n00 = lse2(p00+q00, p01+q10);
    const float n01 = lse2(p00+q01, p01+q11);
    const float n10 = lse2(p10+q00, p11+q10);
    const float n11 = lse2(p10+q01, p11+q11);
    p00=n00; p01=n01; p10=n10; p11=n11;
}
__device__ __forceinline__ void ffma2(ull &d, ull a, ull b){
    asm("fma.rn.f32x2 %0, %1, %2, %0;" : "+l"(d) : "l"(a), "l"(b));
}
__device__ __forceinline__ ull addf2(ull a, ull b){
    ull r; asm("add.rn.f32x2 %0, %1, %2;" : "=l"(r) : "l"(a), "l"(b)); return r;
}
__device__ __forceinline__ ull pack2(float lo, float hi){
    ull r; asm("mov.b64 %0, {%1, %2};" : "=l"(r) : "r"(__float_as_uint(lo)), "r"(__float_as_uint(hi))); return r;
}
__device__ __forceinline__ float2 unpk(ull v){
    unsigned lo, hi; asm("mov.b64 {%0, %1}, %2;" : "=r"(lo), "=r"(hi) : "l"(v));
    return make_float2(__uint_as_float(lo), __uint_as_float(hi));
}
__device__ __forceinline__ void splitpack(float a, float b, unsigned &hw, unsigned &lw){
    __nv_bfloat16 ha = __float2bfloat16_rn(a);
    __nv_bfloat16 hb = __float2bfloat16_rn(b);
    __nv_bfloat16 la = __float2bfloat16_rn(a - __bfloat162float(ha));
    __nv_bfloat16 lb = __float2bfloat16_rn(b - __bfloat162float(hb));
    hw = ((unsigned)__bfloat16_as_ushort(hb) << 16) | (unsigned)__bfloat16_as_ushort(ha);
    lw = ((unsigned)__bfloat16_as_ushort(lb) << 16) | (unsigned)__bfloat16_as_ushort(la);
}
__device__ __forceinline__ void cpasync16(unsigned dst, const void* src){
    asm volatile("cp.async.cg.shared.global [%0], [%1], 16;" :: "r"(dst), "l"(src));
}
#define LDSM4(d0,d1,d2,d3,addr) \
    asm volatile("ldmatrix.sync.aligned.m8n8.x4.shared.b16 {%0,%1,%2,%3}, [%4];" \
        : "=r"(d0),"=r"(d1),"=r"(d2),"=r"(d3) : "r"(addr))
#define MMA_BF16(c,a,b0v,b1v) \
    asm volatile("mma.sync.aligned.m16n8k16.row.col.f32.bf16.bf16.f32 " \
        "{%0,%1,%2,%3}, {%4,%5,%6,%7}, {%8,%9}, {%0,%1,%2,%3};" \
        : "+f"(c[0]),"+f"(c[1]),"+f"(c[2]),"+f"(c[3]) \
        : "r"(a[0]),"r"(a[1]),"r"(a[2]),"r"(a[3]), "r"(b0v),"r"(b1v))

// ---------------------------------------------------------------------------
// Kernel 0a: prep A gather (len-skipped) + B weights.
// ---------------------------------------------------------------------------
#define PREP_A_BLOCKS 2816
#define PREP_B_BLOCKS 176
#define PREP_AB_BLOCKS (PREP_A_BLOCKS + PREP_B_BLOCKS)

__global__ void __launch_bounds__(256)
prep_ab_kernel(const int* __restrict__ sents, const int* __restrict__ masks,
               const int* __restrict__ lens,
               const float* __restrict__ we, const float* __restrict__ me,
               const float* __restrict__ w_ih_f, const float* __restrict__ w_ih_b) {
    const int bid = blockIdx.x;
    const int t = threadIdx.x;
    if (bid < PREP_A_BLOCKS) {
        const int idx = bid*256 + t;
        const int m = idx / 44;
        const int k0 = (idx % 44) * 8;
        const int l = m & 255, bb = m >> 8;
        if (l >= ((lens[bb] + 63) & ~63)) return;
        float v[8];
        if (k0 + 7 < En) {
            const float4* p = (const float4*)(we + (size_t)__ldg(&sents[m])*En + k0);
            const float4 x0 = p[0], x1 = p[1];
            v[0]=x0.x; v[1]=x0.y; v[2]=x0.z; v[3]=x0.w;
            v[4]=x1.x; v[5]=x1.y; v[6]=x1.z; v[7]=x1.w;
        } else {
            const int s = sents[m], mk = masks[m];
            #pragma unroll
            for (int j=0;j<8;j++){
                const int k = k0+j;
                v[j] = (k < En) ? we[(size_t)s*En + k]
                     : (k < Dn) ? me[(size_t)mk*Mn + (k-En)] : 0.f;
            }
        }
        const size_t dsto = ((size_t)m*KPAD + k0)*2;
        unsigned hw[4], lw[4];
        #pragma unroll
        for (int j=0;j<4;j++) splitpack(v[2*j], v[2*j+1], hw[j], lw[j]);
        *(uint4*)((char*)g_A_hi + dsto) = make_uint4(hw[0],hw[1],hw[2],hw[3]);
        *(uint4*)((char*)g_A_lo + dsto) = make_uint4(lw[0],lw[1],lw[2],lw[3]);
    } else {
        const int idx = (bid-PREP_A_BLOCKS)*256 + t;
        const int d = idx / (Gn*44);
        const int rem = idx % (Gn*44);
        const int n = rem / 44;
        const int k0 = (rem % 44) * 8;
        const float* __restrict__ W = d ? w_ih_b : w_ih_f;
        float v[8];
        #pragma unroll
        for (int j=0;j<8;j++){
            const int k = k0+j;
            v[j] = (k < Dn) ? W[(size_t)n*Dn + k] : 0.f;
        }
        const size_t dsto = (((size_t)d*Gn + n)*KPAD + k0)*2;
        unsigned hw[4], lw[4];
        #pragma unroll
        for (int j=0;j<4;j++) splitpack(v[2*j], v[2*j+1], hw[j], lw[j]);
        *(uint4*)((char*)g_B_hi + dsto) = make_uint4(hw[0],hw[1],hw[2],hw[3]);
        *(uint4*)((char*)g_B_lo + dsto) = make_uint4(lw[0],lw[1],lw[2],lw[3]);
    }
}

// ---------------------------------------------------------------------------
// Kernel 0b: LSTM weight repack.
// ---------------------------------------------------------------------------
__global__ void __launch_bounds__(256)
prep_w_kernel(const float* __restrict__ w_hh_f, const float* __restrict__ w_hh_b) {
    const int idx = blockIdx.x*256 + threadIdx.x;  // [0,16384)
    const int d = idx >> 13;
    const int r = idx & 8191;
    const int q = r >> 8;
    const int tt = r & 255;
    const float* __restrict__ w = d ? w_hh_b : w_hh_f;
    const int e = tt >> 1, half = tt & 1;
    const int gA = half*128 + e;
    const int gB = gA + 256;
    const float4 a = *(const float4*)&w[(size_t)gA*HDn + 4*q];
    const float4 b = *(const float4*)&w[(size_t)gB*HDn + 4*q];
    ulonglong2 ua, ub;
    ua.x = pack2(a.x, a.y); ua.y = pack2(a.z, a.w);
    ub.x = pack2(b.x, b.y); ub.y = pack2(b.z, b.w);
    if (q < KRQ) {
        g_wrA[((size_t)d*KRQ + q)*256 + tt] = ua;
        g_wrB[((size_t)d*KRQ + q)*256 + tt] = ub;
    } else {
        g_wsA[((size_t)d*KSQ + (q-KRQ))*256 + tt] = ua;
        g_wsB[((size_t)d*KSQ + (q-KRQ))*256 + tt] = ub;
    }
}

__global__ void warm_kernel() {
    if (threadIdx.x == 0 && blockIdx.x == 0) g_spsum[0] = 0.f;  // crf overwrites
}

// ---------------------------------------------------------------------------
// Kernel 1: bf16 hi/lo tensor-core GEMM -> fp32 gates (+bias). 64x128 m-tiles.
// ---------------------------------------------------------------------------
#define NKT 11
#define GROW 80
#define ABUF (64*GROW)
#define BBUF (128*GROW)
#define GSM_AH 0
#define GSM_AL (2*ABUF)
#define GSM_BH (4*ABUF)
#define GSM_BL (4*ABUF + 2*BBUF)
#define GSM_BIAS (4*ABUF + 4*BBUF)
#define GEMM_SMEM (4*ABUF + 4*BBUF + 512)

__global__ void __launch_bounds__(256, 2)
gemm_gates_kernel(const int* __restrict__ lens,
                  const float* __restrict__ b_ih_f, const float* __restrict__ b_hh_f,
                  const float* __restrict__ b_ih_b, const float* __restrict__ b_hh_b) {
    extern __shared__ char gsm[];
    const int dir = blockIdx.z;
    const int bx = blockIdx.x;
    const int m0 = bx*64;
    const int n0 = blockIdx.y*128;
    if ((bx & 3)*64 >= lens[bx >> 2]) return;

    const float* __restrict__ bih = dir ? b_ih_b : b_ih_f;
    const float* __restrict__ bhh = dir ? b_hh_b : b_hh_f;
    float* __restrict__ C = dir ? g_gates_b : g_gates_f;

    const int tid = threadIdx.x;
    float* bias_s = (float*)(gsm + GSM_BIAS);
    if (tid < 128) bias_s[tid] = bih[n0+tid] + bhh[n0+tid];

    const unsigned smb = (unsigned)__cvta_generic_to_shared(gsm);

    const int cg = tid & 3, r0 = tid >> 2;
    const __nv_bfloat16* __restrict__ Ahi = g_A_hi + (size_t)m0*KPAD;
    const __nv_bfloat16* __restrict__ Alo = g_A_lo + (size_t)m0*KPAD;
    const __nv_bfloat16* __restrict__ Bhi = g_B_hi + ((size_t)dir*Gn + n0)*KPAD;
    const __nv_bfloat16* __restrict__ Blo = g_B_lo + ((size_t)dir*Gn + n0)*KPAD;

    auto issue = [&](int kt, int buf){
        const int kb = kt*32 + cg*8;
        {
            const unsigned d0 = buf*ABUF + r0*GROW + cg*16;
            const size_t so = (size_t)r0*KPAD + kb;
            cpasync16(smb + GSM_AH + d0, Ahi + so);
            cpasync16(smb + GSM_AL + d0, Alo + so);
        }
        #pragma unroll
        for (int p = 0; p < 2; p++){
            const int r = r0 + p*64;
            const unsigned d0 = buf*BBUF + r*GROW + cg*16;
            const size_t so = (size_t)r*KPAD + kb;
            cpasync16(smb + GSM_BH + d0, Bhi + so);
            cpasync16(smb + GSM_BL + d0, Blo + so);
        }
        asm volatile("cp.async.commit_group;");
    };

    const int lane = tid & 31, wid = tid >> 5;
    const int wm = wid >> 2, wn = wid & 3;

    float acc[2][4][4];
    #pragma unroll
    for (int i=0;i<2;i++)
        #pragma unroll
        for (int a=0;a<4;a++)
            #pragma unroll
            for (int c=0;c<4;c++) acc[i][a][c] = 0.f;

    const int a_r = lane & 15, a_k8 = lane >> 4;
    const int b_r = lane & 7, b_h = (lane >> 3) & 1, b_k8 = lane >> 4;
    const unsigned a_base = (wm*32 + a_r)*GROW + a_k8*16;
    const unsigned b_base = (wn*32 + b_h*8 + b_r)*GROW + b_k8*16;

    issue(0, 0);
    asm volatile("cp.async.wait_group 0;");
    __syncthreads();

    for (int kt = 0; kt < NKT; kt++){
        const int buf = kt & 1;
        if (kt < NKT-1) issue(kt+1, buf^1);
        const unsigned abufo = buf*ABUF;
        const unsigned bbufo = buf*BBUF;
        #pragma unroll
        for (int kk = 0; kk < 2; kk++){
            unsigned ah[2][4], al[2][4], bh[2][4], bl[2][4];
            #pragma unroll
            for (int i=0;i<2;i++){
                const unsigned aoff = abufo + a_base + i*16*GROW + kk*32;
                LDSM4(ah[i][0],ah[i][1],ah[i][2],ah[i][3], smb + GSM_AH + aoff);
                LDSM4(al[i][0],al[i][1],al[i][2],al[i][3], smb + GSM_AL + aoff);
            }
            #pragma unroll
            for (int j=0;j<2;j++){
                const unsigned boff = bbufo + b_base + j*16*GROW + kk*32;
                LDSM4(bh[j][0],bh[j][1],bh[j][2],bh[j][3], smb + GSM_BH + boff);
                LDSM4(bl[j][0],bl[j][1],bl[j][2],bl[j][3], smb + GSM_BL + boff);
            }
            #pragma unroll
            for (int i=0;i<2;i++)
                #pragma unroll
                for (int a=0;a<4;a++){
                    const int j = a>>1, s = a&1;
                    MMA_BF16(acc[i][a], ah[i], bh[j][s], bh[j][2+s]);
                    MMA_BF16(acc[i][a], al[i], bh[j][s], bh[j][2+s]);
                    MMA_BF16(acc[i][a], ah[i], bl[j][s], bl[j][2+s]);
                }
        }
        if (kt < NKT-1) asm volatile("cp.async.wait_group 0;");
        __syncthreads();
    }

    const int g = lane >> 2, q = lane & 3;
    #pragma unroll
    for (int i=0;i<2;i++){
        const int m = m0 + wm*32 + i*16 + g;
        float* c0p = C + (size_t)m*Gn + n0 + wn*32;
        float* c1p = C + (size_t)(m+8)*Gn + n0 + wn*32;
        #pragma unroll
        for (int a=0;a<4;a++){
            const int nn = a*8 + 2*q;
            const float bb0 = bias_s[wn*32 + nn], bb1 = bias_s[wn*32 + nn + 1];
            *(float2*)(c0p + nn) = make_float2(acc[i][a][0] + bb0, acc[i][a][1] + bb1);
            *(float2*)(c1p + nn) = make_float2(acc[i][a][2] + bb0, acc[i][a][3] + bb1);
        }
    }
}

// ---------------------------------------------------------------------------
// Kernel 2: LSTM recurrence (unchanged — at its crossbar/serial floor).
// ---------------------------------------------------------------------------
#define LSTM_SMEM (2*KSQ*256*16 + 2*128*4)

__global__ void __launch_bounds__(256, 1)
lstm_kernel(const int* __restrict__ lens) {
    extern __shared__ ulonglong2 smem_v[];
    ulonglong2* sA = smem_v;
    ulonglong2* sB = smem_v + KSQ*256;
    float* hs = (float*)(smem_v + 2*KSQ*256);

    const int bx  = blockIdx.x;
    const int dir = bx >> 6;
    const int row = bx & 63;
    const float* __restrict__ gates_in = dir ? g_gates_b : g_gates_f;
    float* __restrict__ h_out          = dir ? g_hb : g_hf;

    const int tid = threadIdx.x;
    const int e = tid >> 1, half = tid & 1;
    const int gA = half*128 + e;
    const int len = lens[row];

    ulonglong2 wA[KRQ], wB[KRQ];
    {
        const ulonglong2* __restrict__ grA = g_wrA + (size_t)dir*KRQ*256;
        const ulonglong2* __restrict__ grB = g_wrB + (size_t)dir*KRQ*256;
        #pragma unroll
        for (int q = 0; q < KRQ; q++) {
            wA[q] = grA[q*256 + tid];
            wB[q] = grB[q*256 + tid];
        }
    }
    {
        const ulonglong2* __restrict__ gsA = g_wsA + (size_t)dir*KSQ*256;
        const ulonglong2* __restrict__ gsB = g_wsB + (size_t)dir*KSQ*256;
        #pragma unroll
        for (int j = 0; j < KSQ; j++) {
            sA[j*256 + tid] = gsA[j*256 + tid];
            sB[j*256 + tid] = gsB[j*256 + tid];
        }
    }
    if (tid < 128) hs[tid] = 0.f;
    float c_reg = 0.f;

    float exA, exB;
    {
        const int u0 = dir ? (len-1) : 0;
        const size_t base = ((size_t)row*Ln + u0)*Gn;
        exA = gates_in[base + gA];
        exB = gates_in[base + gA + 256];
    }
    __syncthreads();

    for (int t = 0; t < len; t++) {
        const int buf = t & 1;
        const float* hcur = hs + buf*128;
        float* hnxt = hs + (buf^1)*128;

        float nA = 0.f, nB = 0.f;
        if (t+1 < len) {
            const int un = dir ? (len-2-t) : (t+1);
            const size_t b2 = ((size_t)row*Ln + un)*Gn;
            nA = gates_in[b2 + gA];
            nB = gates_in[b2 + gA + 256];
        }

        ull a0=0, a1=0, b0=0, b1=0;
        #pragma unroll
        for (int q = 0; q < KRQ; q++) {
            const ulonglong2 hv = *(const ulonglong2*)&hcur[4*q];
            ffma2(a0, wA[q].x, hv.x); ffma2(a1, wA[q].y, hv.y);
            ffma2(b0, wB[q].x, hv.x); ffma2(b1, wB[q].y, hv.y);
        }
        #pragma unroll
        for (int j = 0; j < KSQ; j++) {
            const ulonglong2 hv = *(const ulonglong2*)&hcur[4*(KRQ+j)];
            const ulonglong2 wa = sA[j*256 + tid];
            const ulonglong2 wb = sB[j*256 + tid];
            ffma2(a0, wa.x, hv.x); ffma2(a1, wa.y, hv.y);
            ffma2(b0, wb.x, hv.x); ffma2(b1, wb.y, hv.y);
        }
        const float2 fa = unpk(addf2(a0, a1));
        const float2 fb = unpk(addf2(b0, b1));
        const float gAv = fa.x + fa.y + exA;
        const float gBv = fb.x + fb.y + exB;

        const float pA = __shfl_xor_sync(0xffffffffu, gAv, 1);
        const float pB = __shfl_xor_sync(0xffffffffu, gBv, 1);
        const float gi = half ? pA : gAv;
        const float gg = half ? pB : gBv;
        const float gf = half ? gAv : pA;
        const float go = half ? gBv : pB;

        const float c = sigf(gf)*c_reg + sigf(gi)*tanha(gg);
        const float h = sigf(go)*tanha(c);
        c_reg = c;

        if (!half) {
            const int u = dir ? (len-1-t) : t;
            hnxt[e] = h;
            h_out[((size_t)row*Ln + u)*HDn + e] = h;
        }
        exA = nA; exB = nB;
        __syncthreads();
    }
}

// ---------------------------------------------------------------------------
// Kernel 3: CRF — 1024 threads, warp-scan CRF (2 barriers/scan), shuffle-first
// reductions, fused finalize.
// ---------------------------------------------------------------------------
__global__ void __launch_bounds__(1024)
crf_kernel(const int* __restrict__ masks,
           const int* __restrict__ lens,
           const int* __restrict__ labels,
           const float* __restrict__ f2t_w,
           const float* __restrict__ f2t_b,
           const float* __restrict__ trans,
           const float* __restrict__ f2l_w,
           const float* __restrict__ f2l_b,
           float* __restrict__ out) {
    const int b = blockIdx.x;
    const int tid = threadIdx.x;     // [0,1024)
    const int hh256 = tid & 255;
    const int lq = tid >> 8;
    const int lane = tid & 31, wrp = tid >> 5;

    __shared__ float tv[Hn];
    __shared__ float fw[2*Hn];
    __shared__ float em[Ln][2];
    __shared__ float sp[Ln];
    __shared__ float agg[16*4];
    __shared__ float sagg[16*4];
    __shared__ float part[32];       // reduction partials
    __shared__ float pnum[1024];
    __shared__ int   msk[Ln];
    __shared__ int   scnt[4];
    __shared__ float Ts[4];
    __shared__ float logZ_s, sumsp_s, scores[3];
    __shared__ unsigned lastflag;

    const int len = lens[b];
    if (tid < Ln) msk[tid] = masks[b*Ln + tid];
    if (tid < 2*Hn) fw[tid] = f2t_w[tid];
    if (tid < 4) Ts[tid] = trans[tid];
    __syncthreads();

    const float* __restrict__ hfb = g_hf + (size_t)b*Ln*HDn;
    const float* __restrict__ hbb = g_hb + (size_t)b*Ln*HDn;
    const float* __restrict__ hsel = (hh256 < HDn) ? (hfb + hh256) : (hbb + hh256 - HDn);

    // tavg: 4 l-quarters of 64
    {
        float num = 0.f; int cnt = 0;
        const int lbeg = lq*64, lend = lbeg + 64;
        for (int l = lbeg; l < lend; l++) {
            const int mf = msk[l];
            if (mf) { num += hsel[l*HDn] * (float)mf; cnt += mf; }
        }
        pnum[tid] = num;
        if (hh256 == 0) scnt[lq] = cnt;
        __syncthreads();
        if (tid < Hn)
            tv[tid] = (pnum[tid] + pnum[256+tid] + pnum[512+tid] + pnum[768+tid])
                      / (float)(scnt[0] + scnt[1] + scnt[2] + scnt[3]);
        __syncthreads();
    }

    // emit: 32 warps, warp-per-position
    {
        const float b0 = f2t_b[0], b1 = f2t_b[1];
        for (int l = wrp; l < len; l += 32) {
            const float* hr  = hfb + l*HDn;
            const float* hr2 = hbb + l*HDn;
            float e0 = 0.f, e1 = 0.f;
            #pragma unroll
            for (int q = 0; q < 4; q++) {
                const int hq = lane + q*32;
                const float c  = hr[hq]  + tv[hq];
                const float c2 = hr2[hq] + tv[HDn + hq];
                e0 += c*fw[hq]      + c2*fw[HDn+hq];
                e1 += c*fw[Hn+hq]   + c2*fw[Hn+HDn+hq];
            }
            #pragma unroll
            for (int off = 16; off; off >>= 1) {
                e0 += __shfl_xor_sync(0xffffffffu, e0, off);
                e1 += __shfl_xor_sync(0xffffffffu, e1, off);
            }
            if (lane == 0) { em[l][0] = e0 + b0; em[l][1] = e1 + b1; }
        }
    }
    __syncthreads();

    // ---- prefix scan (threads [0,512), 16 warps): 3-phase warp scan ----
    float p00 = 0.f, p01 = -NEGBIG, p10 = -NEGBIG, p11 = 0.f;
    if (tid >= 1 && tid < len) {
        const float e0 = em[tid][0], e1 = em[tid][1];
        p00 = Ts[0] + e0; p01 = Ts[1] + e1;
        p10 = Ts[2] + e0; p11 = Ts[3] + e1;
    }
    if (tid < 512) {
        #pragma unroll
        for (int d = 1; d < 32; d <<= 1) {
            const float q00 = __shfl_up_sync(0xffffffffu, p00, d);
            const float q01 = __shfl_up_sync(0xffffffffu, p01, d);
            const float q10 = __shfl_up_sync(0xffffffffu, p10, d);
            const float q11 = __shfl_up_sync(0xffffffffu, p11, d);
            if (lane >= d) mcompose_pre(q00,q01,q10,q11, p00,p01,p10,p11);
        }
        if (lane == 31) { agg[wrp*4]=p00; agg[wrp*4+1]=p01; agg[wrp*4+2]=p10; agg[wrp*4+3]=p11; }
    }
    __syncthreads();
    if (wrp == 0) {
        float a00=0.f, a01=-NEGBIG, a10=-NEGBIG, a11=0.f;
        if (lane < 16) { a00=agg[lane*4]; a01=agg[lane*4+1]; a10=agg[lane*4+2]; a11=agg[lane*4+3]; }
        #pragma unroll
        for (int d = 1; d < 16; d <<= 1) {
            const float q00 = __shfl_up_sync(0xffffffffu, a00, d);
            const float q01 = __shfl_up_sync(0xffffffffu, a01, d);
            const float q10 = __shfl_up_sync(0xffffffffu, a10, d);
            const float q11 = __shfl_up_sync(0xffffffffu, a11, d);
            if (lane >= d && lane < 16) mcompose_pre(q00,q01,q10,q11, a00,a01,a10,a11);
        }
        if (lane < 16) { sagg[lane*4]=a00; sagg[lane*4+1]=a01; sagg[lane*4+2]=a10; sagg[lane*4+3]=a11; }
    }
    __syncthreads();
    if (tid < 512 && wrp > 0)
        mcompose_pre(sagg[(wrp-1)*4], sagg[(wrp-1)*4+1], sagg[(wrp-1)*4+2], sagg[(wrp-1)*4+3],
                     p00, p01, p10, p11);
    const float a_t1 = lse2(em[0][0] + p01, em[0][1] + p11);
    if (tid == len-1) {
        const float a_t0 = lse2(em[0][0] + p00, em[0][1] + p10);
        logZ_s = lse2(a_t0, a_t1);
    }
    __syncthreads();

    // ---- suffix scan: R[t] = Q_t ∘ ... ∘ Q_511, Q_t = M_{t+1} ----
    float u00 = 0.f, u01 = -NEGBIG, u10 = -NEGBIG, u11 = 0.f;
    if (tid+1 < len) {
        const float e0 = em[tid+1][0], e1 = em[tid+1][1];
        u00 = Ts[0] + e0; u01 = Ts[1] + e1;
        u10 = Ts[2] + e0; u11 = Ts[3] + e1;
    }
    if (tid < 512) {
        #pragma unroll
        for (int d = 1; d < 32; d <<= 1) {
            const float q00 = __shfl_down_sync(0xffffffffu, u00, d);
            const float q01 = __shfl_down_sync(0xffffffffu, u01, d);
            const float q10 = __shfl_down_sync(0xffffffffu, u10, d);
            const float q11 = __shfl_down_sync(0xffffffffu, u11, d);
            if (lane + d < 32) mcompose_post(u00,u01,u10,u11, q00,q01,q10,q11);
        }
        if (lane == 0) { agg[wrp*4]=u00; agg[wrp*4+1]=u01; agg[wrp*4+2]=u10; agg[wrp*4+3]=u11; }
    }
    __syncthreads();
    if (wrp == 0) {
        float a00=0.f, a01=-NEGBIG, a10=-NEGBIG, a11=0.f;
        if (lane < 16) { a00=agg[lane*4]; a01=agg[lane*4+1]; a10=agg[lane*4+2]; a11=agg[lane*4+3]; }
        #pragma unroll
        for (int d = 1; d < 16; d <<= 1) {
            const float q00 = __shfl_down_sync(0xffffffffu, a00, d);
            const float q01 = __shfl_down_sync(0xffffffffu, a01, d);
            const float q10 = __shfl_down_sync(0xffffffffu, a10, d);
            const float q11 = __shfl_down_sync(0xffffffffu, a11, d);
            if (lane + d < 16) mcompose_post(a00,a01,a10,a11, q00,q01,q10,q11);
        }
        if (lane < 16) { sagg[lane*4]=a00; sagg[lane*4+1]=a01; sagg[lane*4+2]=a10; sagg[lane*4+3]=a11; }
    }
    __syncthreads();
    if (tid < 512 && wrp < 15)
        mcompose_post(u00, u01, u10, u11,
                      sagg[(wrp+1)*4], sagg[(wrp+1)*4+1], sagg[(wrp+1)*4+2], sagg[(wrp+1)*4+3]);
    const float b_t1 = lse2(u10, u11);

    float spv = 0.f;
    if (tid < Ln) {
        spv = (tid < len) ? __expf(a_t1 + b_t1 - logZ_s) : 0.f;
        sp[tid] = spv;
    }
    __syncthreads();

    // sum_sp: warp shuffle + 8 partials (deterministic fixed tree)
    {
        float v = spv;   // nonzero only tid<256 (warps 0..7)
        #pragma unroll
        for (int off = 16; off; off >>= 1) v += __shfl_xor_sync(0xffffffffu, v, off);
        if (lane == 0 && wrp < 8) part[wrp] = v;
    }
    __syncthreads();
    if (tid == 0) {
        float s = 0.f;
        #pragma unroll
        for (int w = 0; w < 8; w++) s += part[w];
        sumsp_s = s;
    }
    __syncthreads();
    const float sum_sp = sumsp_s;

    // sent_v: 4 l-quarters
    {
        float s1 = 0.f;
        const int lbeg = lq*64, lend = lbeg + 64;
        #pragma unroll 8
        for (int l = lbeg; l < lend; l++) s1 += sp[l] * hsel[l*HDn];
        pnum[tid] = s1;
    }
    __syncthreads();
    float svh = 0.f;
    if (tid < Hn)
        svh = pnum[tid] + pnum[256+tid] + pnum[512+tid] + pnum[768+tid] + sum_sp * tv[tid];

    // 3 classifier scores: shuffle-first, one smem round
    {
        float v0 = 0.f, v1 = 0.f, v2 = 0.f;
        if (tid < Hn) {
            v0 = svh * f2l_w[tid];
            v1 = svh * f2l_w[Hn + tid];
            v2 = svh * f2l_w[2*Hn + tid];
        }
        #pragma unroll
        for (int off = 16; off; off >>= 1) {
            v0 += __shfl_xor_sync(0xffffffffu, v0, off);
            v1 += __shfl_xor_sync(0xffffffffu, v1, off);
            v2 += __shfl_xor_sync(0xffffffffu, v2, off);
        }
        if (lane == 0 && wrp < 8) { part[wrp] = v0; part[8+wrp] = v1; part[16+wrp] = v2; }
    }
    __syncthreads();

    if (tid == 0) {
        float s0=0.f, s1=0.f, s2=0.f;
        #pragma unroll
        for (int w = 0; w < 8; w++) { s0 += part[w]; s1 += part[8+w]; s2 += part[16+w]; }
        const float sc0 = s0 + f2l_b[0], sc1 = s1 + f2l_b[1], sc2 = s2 + f2l_b[2];
        const float m = fmaxf(sc0, fmaxf(sc1, sc2));
        const float lse = m + __logf(__expf(sc0-m)+__expf(sc1-m)+__expf(sc2-m));
        const int lb = labels[b];
        const float scl = (lb == 0) ? sc0 : (lb == 1) ? sc1 : sc2;
        g_cls[b]   = lse - scl;
        g_spsum[b] = sum_sp;
        __threadfence();
        lastflag = (atomicAdd(&g_crf_done, 1u) == Bn-1) ? 1u : 0u;
    }
    __syncthreads();

    if (lastflag) {
        if (tid < 64) { pnum[tid] = g_cls[tid]; pnum[64+tid] = g_spsum[tid]; }
        __syncthreads();
        for (int s = 32; s > 0; s >>= 1) {
            if (tid < s) { pnum[tid] += pnum[tid+s]; pnum[64+tid] += pnum[64+tid+s]; }
            __syncthreads();
        }
        if (tid == 0) {
            const float pena = fmaxf(Ts[2]-Ts[0], 0.f) + fmaxf(Ts[1]-Ts[3], 0.f);
            out[0] = pnum[0] / (float)Bn;
            out[1] = 1.0f*pena + 0.1f*(pnum[64]/(float)Bn);
            g_crf_done = 0;
        }
    }
}

extern "C" void kernel_launch(void* const* d_in, const int* in_sizes, int n_in,
                              void* d_out, int out_size) {
    const int*   sents      = (const int*)d_in[0];
    const int*   masks      = (const int*)d_in[1];
    const int*   labels     = (const int*)d_in[2];
    const int*   lens       = (const int*)d_in[3];
    const float* word_embed = (const float*)d_in[4];
    const float* mask_embed = (const float*)d_in[5];
    const float* w_ih_f     = (const float*)d_in[6];
    const float* w_hh_f     = (const float*)d_in[7];
    const float* b_ih_f     = (const float*)d_in[8];
    const float* b_hh_f     = (const float*)d_in[9];
    const float* w_ih_b     = (const float*)d_in[10];
    const float* w_hh_b     = (const float*)d_in[11];
    const float* b_ih_b     = (const float*)d_in[12];
    const float* b_hh_b     = (const float*)d_in[13];
    const float* f2t_w      = (const float*)d_in[14];
    const float* f2t_b      = (const float*)d_in[15];
    const float* trans      = (const float*)d_in[16];
    const float* f2l_w      = (const float*)d_in[17];
    const float* f2l_b      = (const float*)d_in[18];
    float* out = (float*)d_out;

    cudaFuncSetAttribute(lstm_kernel,
                         cudaFuncAttributeMaxDynamicSharedMemorySize, LSTM_SMEM);
    cudaFuncSetAttribute(gemm_gates_kernel,
                         cudaFuncAttributeMaxDynamicSharedMemorySize, GEMM_SMEM);

    prep_ab_kernel<<<PREP_AB_BLOCKS, 256>>>(sents, masks, lens,   // launch 1
                                            word_embed, mask_embed, w_ih_f, w_ih_b);
    prep_w_kernel<<<64, 256>>>(w_hh_f, w_hh_b);                   // launch 2
    warm_kernel<<<1, 32>>>();                                     // launch 3
    dim3 ggrid(Bn*Ln/64, Gn/128, 2);
    gemm_gates_kernel<<<ggrid, 256, GEMM_SMEM>>>(lens,            // launch 4 (captured)
                                                 b_ih_f, b_hh_f, b_ih_b, b_hh_b);
    lstm_kernel<<<2*Bn, 256, LSTM_SMEM>>>(lens);                  // launch 5
    crf_kernel<<<Bn, 1024>>>(masks, lens, labels, f2t_w, f2t_b,   // launch 6
                             trans, f2l_w, f2l_b, out);
}